// round 12
// baseline (speedup 1.0000x reference)
#include <cuda_runtime.h>

// CVCalculator: sliding-window CV, W=60, ddof=1, eps=1e-6.
// flow (16,4096,64) fp32 -> out (16,4096,64), first 59 time rows zero.
//
// Gold-matching cumsum = XLA ReduceWindowRewriter blocked scan, base 16
// (verified R8/R10/R11): inner0 = seq scan within 16-blocks; carries scanned
// within 16-groups; group totals scanned; S1[b]=fl(S2[g-1]+inner1[b]);
// cs[t]=fl(S1[b-1]+inner0[t]). Pole-critical epilogue ops kept exact:
// mean = div.rn(s1,60); denom = fl(mean+1e-6f). Numerator relaxed (rel ~1e-7).
//
// R12: staging pass removed. Each P1 thread loads its 16-block directly from
// global (16 independent LDG.128, same 50% sector efficiency the staged load
// had), squares in registers for kind1, scans in registers, and cs is written
// to smem exactly once in P5. Layout [kind][block][ti][feat4], stride 68
// floats => all LDS/STS.128 conflict-free.

#define T_     4096
#define NT     512
#define KSTR   17408                  // 256 blocks * 68 floats per kind
#define CB     (2 * KSTR)             // carries base  (34816)
#define CKSTR  1104                   // 16 groups * 68 + pad
#define GB     (CB + 2 * CKSTR)       // group-total base (37024)
#define GKSTR  68
#define SMEM_BYTES ((GB + 2 * GKSTR) * 4)   // 148640 B

__device__ __forceinline__ int taddr(int kind, int t) {
    return kind * KSTR + (t >> 4) * 68 + (t & 15) * 4;
}
__device__ __forceinline__ float4 f4addv(float4 a, float4 v) {
    float4 r;
    r.x = __fadd_rn(a.x, v.x); r.y = __fadd_rn(a.y, v.y);
    r.z = __fadd_rn(a.z, v.z); r.w = __fadd_rn(a.w, v.w);
    return r;
}

extern "C" __global__ void __launch_bounds__(NT, 1)
cv_kernel(const float* __restrict__ in, float* __restrict__ out)
{
    extern __shared__ float S[];
    const int tid = threadIdx.x;
    const int bat = blockIdx.x >> 4;
    const int fb  = (blockIdx.x & 15) * 4;

    const float* __restrict__ gin  = in  + (size_t)bat * T_ * 64 + fb;
    float* __restrict__       gout = out + (size_t)bat * T_ * 64 + fb;

    // ---- P1: direct global load of one 16-block, scan in registers ----
    const int kind = tid >> 8;
    const int blk  = tid & 255;
    const float* __restrict__ gp = gin + (size_t)(blk << 4) * 64;

    float4 r[16];
    #pragma unroll
    for (int i = 0; i < 16; ++i)        // 16 independent LDG.128 (MLP=16)
        r[i] = *reinterpret_cast<const float4*>(gp + (size_t)i * 64);
    if (kind) {
        #pragma unroll
        for (int i = 0; i < 16; ++i) {
            r[i].x = __fmul_rn(r[i].x, r[i].x);
            r[i].y = __fmul_rn(r[i].y, r[i].y);
            r[i].z = __fmul_rn(r[i].z, r[i].z);
            r[i].w = __fmul_rn(r[i].w, r[i].w);
        }
    }
    #pragma unroll
    for (int i = 1; i < 16; ++i)
        r[i] = f4addv(r[i - 1], r[i]);
    // block total -> carries
    *reinterpret_cast<float4*>(S + CB + kind * CKSTR + (blk >> 4) * 68
                               + (blk & 15) * 4) = r[15];
    __syncthreads();

    // ---- P2: scan carries within 16-groups (warp 0, one lane per unit) ----
    if (tid < 32) {
        const int kk = tid >> 4, g = tid & 15;
        float* __restrict__ c = S + CB + kk * CKSTR + g * 68;
        float4 acc = make_float4(0.f, 0.f, 0.f, 0.f);
        #pragma unroll
        for (int i = 0; i < 16; ++i) {
            float4 v = *reinterpret_cast<const float4*>(c + 4 * i);
            acc = f4addv(acc, v);
            *reinterpret_cast<float4*>(c + 4 * i) = acc;   // inner1 inclusive
        }
        *reinterpret_cast<float4*>(S + GB + kk * GKSTR + g * 4) = acc;
    }
    __syncwarp();
    // ---- P3: scan 16 group totals per kind (lanes 0,1 of warp 0) ----
    if (tid < 2) {
        float* __restrict__ gbuf = S + GB + tid * GKSTR;
        float4 acc = make_float4(0.f, 0.f, 0.f, 0.f);
        #pragma unroll
        for (int g = 0; g < 16; ++g) {
            float4 v = *reinterpret_cast<const float4*>(gbuf + 4 * g);
            acc = f4addv(acc, v);
            *reinterpret_cast<float4*>(gbuf + 4 * g) = acc; // S2 inclusive
        }
    }
    __syncthreads();

    // ---- P5 (P4 folded): cs = fl(S1[blk-1] + inner0), write once ----
    float* __restrict__ base = S + kind * KSTR + blk * 68;
    if (blk > 0) {
        const int pb = blk - 1, pg = pb >> 4;
        float4 carry = *reinterpret_cast<const float4*>(
            S + CB + kind * CKSTR + pg * 68 + (pb & 15) * 4);   // inner1[pb]
        if (pg > 0) {
            float4 s2 = *reinterpret_cast<const float4*>(
                S + GB + kind * GKSTR + (pg - 1) * 4);
            // S1[pb] = fl(S2[pg-1] + inner1[pb])
            carry.x = __fadd_rn(s2.x, carry.x);
            carry.y = __fadd_rn(s2.y, carry.y);
            carry.z = __fadd_rn(s2.z, carry.z);
            carry.w = __fadd_rn(s2.w, carry.w);
        }
        #pragma unroll
        for (int i = 0; i < 16; ++i) {
            float4 v;
            v.x = __fadd_rn(carry.x, r[i].x);
            v.y = __fadd_rn(carry.y, r[i].y);
            v.z = __fadd_rn(carry.z, r[i].z);
            v.w = __fadd_rn(carry.w, r[i].w);
            *reinterpret_cast<float4*>(base + 4 * i) = v;
        }
    } else {
        #pragma unroll
        for (int i = 0; i < 16; ++i)
            *reinterpret_cast<float4*>(base + 4 * i) = r[i];
    }
    __syncthreads();

    // ---- epilogue: 4x LDS.128 + math + STG.128 per t ----
    #pragma unroll 4
    for (int k = 0; k < 8; ++k) {
        const int t = tid + (k << 9);
        float4 o;
        if (t < 59) {
            o = make_float4(0.f, 0.f, 0.f, 0.f);
        } else {
            float4 c1 = *reinterpret_cast<const float4*>(S + taddr(0, t));
            float4 c2 = *reinterpret_cast<const float4*>(S + taddr(1, t));
            float4 p1 = make_float4(0.f, 0.f, 0.f, 0.f);
            float4 p2 = make_float4(0.f, 0.f, 0.f, 0.f);
            if (t >= 60) {
                p1 = *reinterpret_cast<const float4*>(S + taddr(0, t - 60));
                p2 = *reinterpret_cast<const float4*>(S + taddr(1, t - 60));
            }
            const float* c1a = &c1.x; const float* c2a = &c2.x;
            const float* p1a = &p1.x; const float* p2a = &p2.x;
            float* oa = &o.x;
            #pragma unroll
            for (int f = 0; f < 4; ++f) {
                float s1 = __fsub_rn(c1a[f], p1a[f]);
                float s2 = __fsub_rn(c2a[f], p2a[f]);
                float mean  = __fdiv_rn(s1, 60.0f);      // pole-critical
                float denom = __fadd_rn(mean, 1e-6f);    // pole-critical
                float var = __fmul_rn(__fmaf_rn(-s1, mean, s2), 1.0f / 59.0f);
                float std = (var > 0.0f)
                          ? __fmul_rn(var, __frsqrt_rn(var)) : 0.0f;
                oa[f] = __fdividef(std, denom);
            }
        }
        *reinterpret_cast<float4*>(gout + (size_t)t * 64) = o;
    }
}

extern "C" void kernel_launch(void* const* d_in, const int* in_sizes, int n_in,
                              void* d_out, int out_size) {
    (void)in_sizes; (void)n_in; (void)out_size;
    cudaFuncSetAttribute(cv_kernel, cudaFuncAttributeMaxDynamicSharedMemorySize,
                         SMEM_BYTES);
    cv_kernel<<<256, NT, SMEM_BYTES>>>((const float*)d_in[0], (float*)d_out);
}

// round 13
// speedup vs baseline: 1.0822x; 1.0822x over previous
#include <cuda_runtime.h>

// CVCalculator: sliding-window CV, W=60, ddof=1, eps=1e-6.
// flow (16,4096,64) fp32 -> out (16,4096,64), first 59 time rows zero.
//
// Gold-matching cumsum = XLA ReduceWindowRewriter blocked scan, base 16
// (verified R8/R10/R11): inner0 = seq scan within 16-blocks; carries scanned
// within 16-groups; group totals scanned; S1[b]=fl(S2[g-1]+inner1[b]);
// cs[t]=fl(S1[b-1]+inner0[t]). Pole-critical epilogue ops kept exact:
// mean = div.rn(s1,60); denom = fl(mean+1e-6f). Numerator relaxed (rel ~1e-7).
//
// R13: (a) input staged ONCE via cp.async (16B) into the kind0 region; kind1
// threads read it from smem and square in registers (no duplicate LDG, no
// kind1 staging STS). (b) P2/P3 carry scans prefetch all 16 values before the
// add chain (serial section ~3x shorter). Layout [kind][block][ti][feat4],
// block stride 68 floats => all LDS/STS.128 conflict-free.

#define T_     4096
#define NT     512
#define KSTR   17408                  // 256 blocks * 68 floats per kind
#define CB     (2 * KSTR)             // carries base  (34816)
#define CKSTR  1104                   // 16 groups * 68 + pad
#define GB     (CB + 2 * CKSTR)       // group-total base (37024)
#define GKSTR  68
#define SMEM_BYTES ((GB + 2 * GKSTR) * 4)   // 148640 B

__device__ __forceinline__ int taddr(int kind, int t) {
    return kind * KSTR + (t >> 4) * 68 + (t & 15) * 4;
}
__device__ __forceinline__ float4 f4addv(float4 a, float4 v) {
    float4 r;
    r.x = __fadd_rn(a.x, v.x); r.y = __fadd_rn(a.y, v.y);
    r.z = __fadd_rn(a.z, v.z); r.w = __fadd_rn(a.w, v.w);
    return r;
}
__device__ __forceinline__ void cp_async16(float* dst, const float* src) {
    unsigned d = (unsigned)__cvta_generic_to_shared(dst);
    asm volatile("cp.async.cg.shared.global [%0], [%1], 16;"
                 :: "r"(d), "l"(src) : "memory");
}

extern "C" __global__ void __launch_bounds__(NT, 1)
cv_kernel(const float* __restrict__ in, float* __restrict__ out)
{
    extern __shared__ float S[];
    const int tid = threadIdx.x;
    const int bat = blockIdx.x >> 4;
    const int fb  = (blockIdx.x & 15) * 4;

    const float* __restrict__ gin  = in  + (size_t)bat * T_ * 64 + fb;
    float* __restrict__       gout = out + (size_t)bat * T_ * 64 + fb;

    // ---- stage x once: global -> kind0 region via cp.async ----
    #pragma unroll
    for (int k = 0; k < 8; ++k) {
        const int t = tid + (k << 9);
        cp_async16(S + taddr(0, t), gin + (size_t)t * 64);
    }
    asm volatile("cp.async.commit_group;" ::: "memory");
    asm volatile("cp.async.wait_group 0;" ::: "memory");
    __syncthreads();

    // ---- P1: read 16-block from kind0 region; square if kind1; scan ----
    const int kind = tid >> 8;
    const int blk  = tid & 255;
    const float* __restrict__ xbase = S + blk * 68;   // x lives in kind0 region

    float4 r[16];
    #pragma unroll
    for (int i = 0; i < 16; ++i)
        r[i] = *reinterpret_cast<const float4*>(xbase + 4 * i);
    if (kind) {
        #pragma unroll
        for (int i = 0; i < 16; ++i) {
            r[i].x = __fmul_rn(r[i].x, r[i].x);
            r[i].y = __fmul_rn(r[i].y, r[i].y);
            r[i].z = __fmul_rn(r[i].z, r[i].z);
            r[i].w = __fmul_rn(r[i].w, r[i].w);
        }
    }
    #pragma unroll
    for (int i = 1; i < 16; ++i)
        r[i] = f4addv(r[i - 1], r[i]);
    // block total -> carries
    *reinterpret_cast<float4*>(S + CB + kind * CKSTR + (blk >> 4) * 68
                               + (blk & 15) * 4) = r[15];
    __syncthreads();

    // ---- P2: scan carries within 16-groups (warp 0; prefetch then chain) ----
    if (tid < 32) {
        const int kk = tid >> 4, g = tid & 15;
        float* __restrict__ c = S + CB + kk * CKSTR + g * 68;
        float4 v[16];
        #pragma unroll
        for (int i = 0; i < 16; ++i)
            v[i] = *reinterpret_cast<const float4*>(c + 4 * i);
        #pragma unroll
        for (int i = 1; i < 16; ++i)
            v[i] = f4addv(v[i - 1], v[i]);
        #pragma unroll
        for (int i = 0; i < 16; ++i)
            *reinterpret_cast<float4*>(c + 4 * i) = v[i];   // inner1 inclusive
        *reinterpret_cast<float4*>(S + GB + kk * GKSTR + g * 4) = v[15];
    }
    __syncwarp();
    // ---- P3: scan 16 group totals per kind (lanes 0,1; prefetch+chain) ----
    if (tid < 2) {
        float* __restrict__ gbuf = S + GB + tid * GKSTR;
        float4 v[16];
        #pragma unroll
        for (int g = 0; g < 16; ++g)
            v[g] = *reinterpret_cast<const float4*>(gbuf + 4 * g);
        #pragma unroll
        for (int g = 1; g < 16; ++g)
            v[g] = f4addv(v[g - 1], v[g]);
        #pragma unroll
        for (int g = 0; g < 16; ++g)
            *reinterpret_cast<float4*>(gbuf + 4 * g) = v[g]; // S2 inclusive
    }
    __syncthreads();

    // ---- P5 (P4 folded): cs = fl(S1[blk-1] + inner0), write once ----
    float* __restrict__ base = S + kind * KSTR + blk * 68;
    if (blk > 0) {
        const int pb = blk - 1, pg = pb >> 4;
        float4 carry = *reinterpret_cast<const float4*>(
            S + CB + kind * CKSTR + pg * 68 + (pb & 15) * 4);   // inner1[pb]
        if (pg > 0) {
            float4 s2 = *reinterpret_cast<const float4*>(
                S + GB + kind * GKSTR + (pg - 1) * 4);
            // S1[pb] = fl(S2[pg-1] + inner1[pb])
            carry.x = __fadd_rn(s2.x, carry.x);
            carry.y = __fadd_rn(s2.y, carry.y);
            carry.z = __fadd_rn(s2.z, carry.z);
            carry.w = __fadd_rn(s2.w, carry.w);
        }
        #pragma unroll
        for (int i = 0; i < 16; ++i) {
            float4 v;
            v.x = __fadd_rn(carry.x, r[i].x);
            v.y = __fadd_rn(carry.y, r[i].y);
            v.z = __fadd_rn(carry.z, r[i].z);
            v.w = __fadd_rn(carry.w, r[i].w);
            *reinterpret_cast<float4*>(base + 4 * i) = v;
        }
    } else {
        #pragma unroll
        for (int i = 0; i < 16; ++i)
            *reinterpret_cast<float4*>(base + 4 * i) = r[i];
    }
    __syncthreads();

    // ---- epilogue: 4x LDS.128 + math + STG.128 per t ----
    #pragma unroll 4
    for (int k = 0; k < 8; ++k) {
        const int t = tid + (k << 9);
        float4 o;
        if (t < 59) {
            o = make_float4(0.f, 0.f, 0.f, 0.f);
        } else {
            float4 c1 = *reinterpret_cast<const float4*>(S + taddr(0, t));
            float4 c2 = *reinterpret_cast<const float4*>(S + taddr(1, t));
            float4 p1 = make_float4(0.f, 0.f, 0.f, 0.f);
            float4 p2 = make_float4(0.f, 0.f, 0.f, 0.f);
            if (t >= 60) {
                p1 = *reinterpret_cast<const float4*>(S + taddr(0, t - 60));
                p2 = *reinterpret_cast<const float4*>(S + taddr(1, t - 60));
            }
            const float* c1a = &c1.x; const float* c2a = &c2.x;
            const float* p1a = &p1.x; const float* p2a = &p2.x;
            float* oa = &o.x;
            #pragma unroll
            for (int f = 0; f < 4; ++f) {
                float s1 = __fsub_rn(c1a[f], p1a[f]);
                float s2 = __fsub_rn(c2a[f], p2a[f]);
                float mean  = __fdiv_rn(s1, 60.0f);      // pole-critical
                float denom = __fadd_rn(mean, 1e-6f);    // pole-critical
                float var = __fmul_rn(__fmaf_rn(-s1, mean, s2), 1.0f / 59.0f);
                float std = (var > 0.0f)
                          ? __fmul_rn(var, __frsqrt_rn(var)) : 0.0f;
                oa[f] = __fdividef(std, denom);
            }
        }
        *reinterpret_cast<float4*>(gout + (size_t)t * 64) = o;
    }
}

extern "C" void kernel_launch(void* const* d_in, const int* in_sizes, int n_in,
                              void* d_out, int out_size) {
    (void)in_sizes; (void)n_in; (void)out_size;
    cudaFuncSetAttribute(cv_kernel, cudaFuncAttributeMaxDynamicSharedMemorySize,
                         SMEM_BYTES);
    cv_kernel<<<256, NT, SMEM_BYTES>>>((const float*)d_in[0], (float*)d_out);
}